// round 1
// baseline (speedup 1.0000x reference)
#include <cuda_runtime.h>

// Attention_72447508349519 — algebraic collapse:
//   softmax rows sum to 1 and einsum('bqk,bvd->bqd') contracts k and v
//   independently, so out[b,q,d] = sum_n v[b,n,d] for every q.
//   => GroupNorm stats + per-channel weighted sums (1 pass over x),
//      two 16x1024x1024 GEMVs (Wv then Wo), broadcast-write the result.
// Unused inputs: Wq,bq,Wk,bk.

#define BSZ   16
#define CDIM  1024   // channels c (== DIM)
#define NPOS  1024   // N = h*w
#define NGRP  32     // GroupNorm groups (along N)
#define GROWS 32     // N-rows per group
#define EPS   1e-5f

// Scratch (static device globals — no dynamic allocation).
__device__ float g_P[BSZ * NGRP * CDIM];   // P[b,g,c] = sum_{n in g} gamma[n]*x[b,c,n]
__device__ float g_mean[BSZ * NGRP];
__device__ float g_rstd[BSZ * NGRP];
__device__ float g_s[BSZ * CDIM];          // s[b,c] = sum_n norm_x[b,n,c]
__device__ float g_vsum[BSZ * CDIM];       // vsum[b,d] = sum_n v[b,n,d]

// ---------------------------------------------------------------------------
// k1: per (b,g) block — one pass over the 32x1024 slab of x.
// Computes group mean/rstd and gamma-weighted per-channel partial sums P.
// Lane mapping: 8 lanes per channel-row (one float4 each) => every warp
// LDG.128 touches exactly 4 fully-used 128B lines.
// ---------------------------------------------------------------------------
__global__ __launch_bounds__(256) void k1_stats(const float* __restrict__ x,
                                                const float* __restrict__ gamma) {
    const int b = blockIdx.x >> 5;
    const int g = blockIdx.x & 31;
    const int tid = threadIdx.x;

    __shared__ float sg[GROWS];
    if (tid < GROWS) sg[tid] = gamma[g * GROWS + tid];
    __syncthreads();

    const int fj = tid & 7;    // float4 slot within the 32-float row
    const int gq = tid >> 3;   // row-group 0..31 (channel = gq + 32*k)
    const float w0 = sg[fj * 4 + 0], w1 = sg[fj * 4 + 1];
    const float w2 = sg[fj * 4 + 2], w3 = sg[fj * 4 + 3];

    const float* xb = x + (size_t)b * CDIM * NPOS + g * GROWS;

    float tsum = 0.f, tsq = 0.f;
    #pragma unroll 4
    for (int k = 0; k < 32; k++) {
        const int c = gq + 32 * k;
        const float4 v = reinterpret_cast<const float4*>(xb + (size_t)c * NPOS)[fj];
        tsum += v.x + v.y + v.z + v.w;
        tsq  += v.x * v.x + v.y * v.y + v.z * v.z + v.w * v.w;
        float pw = w0 * v.x + w1 * v.y + w2 * v.z + w3 * v.w;
        // reduce the 8 lanes covering this row (xor over lane bits 0..2)
        pw += __shfl_xor_sync(0xFFFFFFFFu, pw, 1);
        pw += __shfl_xor_sync(0xFFFFFFFFu, pw, 2);
        pw += __shfl_xor_sync(0xFFFFFFFFu, pw, 4);
        if (fj == 0) g_P[(b * NGRP + g) * CDIM + c] = pw;
    }

    // Block reduction of tsum/tsq over all 256 threads.
    #pragma unroll
    for (int o = 16; o; o >>= 1) {
        tsum += __shfl_xor_sync(0xFFFFFFFFu, tsum, o);
        tsq  += __shfl_xor_sync(0xFFFFFFFFu, tsq,  o);
    }
    __shared__ float reds[8], redq[8];
    const int wid = tid >> 5, lane = tid & 31;
    if (lane == 0) { reds[wid] = tsum; redq[wid] = tsq; }
    __syncthreads();
    if (tid == 0) {
        float S = 0.f, Q = 0.f;
        #pragma unroll
        for (int w = 0; w < 8; w++) { S += reds[w]; Q += redq[w]; }
        const float inv = 1.f / (float)(GROWS * CDIM);
        const float m = S * inv;
        const float var = Q * inv - m * m;
        g_mean[b * NGRP + g] = m;
        g_rstd[b * NGRP + g] = rsqrtf(var + EPS);
    }
}

// ---------------------------------------------------------------------------
// k2: s[b,c] = sum_g rstd[b,g]*(P[b,g,c] - mean[b,g]*Gam_g) + sum_n beta[n]
// ---------------------------------------------------------------------------
__global__ __launch_bounds__(1024) void k2_colsum(const float* __restrict__ gamma,
                                                  const float* __restrict__ beta) {
    const int b = blockIdx.x;
    const int tid = threadIdx.x;

    __shared__ float sgam[CDIM];
    __shared__ float sGam[NGRP];
    __shared__ float sm[NGRP], sr[NGRP];
    __shared__ float redb[32];
    __shared__ float sB;

    sgam[tid] = gamma[tid];
    float bb = beta[tid];
    #pragma unroll
    for (int o = 16; o; o >>= 1) bb += __shfl_xor_sync(0xFFFFFFFFu, bb, o);
    const int wid = tid >> 5, lane = tid & 31;
    if (lane == 0) redb[wid] = bb;
    if (tid < NGRP) { sm[tid] = g_mean[b * NGRP + tid]; sr[tid] = g_rstd[b * NGRP + tid]; }
    __syncthreads();

    if (tid < NGRP) {
        float t = 0.f;
        #pragma unroll
        for (int j = 0; j < GROWS; j++) t += sgam[tid * GROWS + j];
        sGam[tid] = t;
    }
    if (tid == 0) {
        float t = 0.f;
        #pragma unroll
        for (int w = 0; w < 32; w++) t += redb[w];
        sB = t;
    }
    __syncthreads();

    float acc = sB;
    const float* Pb = g_P + b * NGRP * CDIM + tid;
    #pragma unroll
    for (int g = 0; g < NGRP; g++)
        acc += sr[g] * (Pb[g * CDIM] - sm[g] * sGam[g]);
    g_s[b * CDIM + tid] = acc;
}

// ---------------------------------------------------------------------------
// k3: vsum[b,d] = s[b,:] . Wv[d,:] + 1024*bv[d]
// grid (128, 2): x = group of 8 output rows d, y = batch half (8 batches).
// One warp per d; lanes stride c with float4; 8-batch accumulators.
// ---------------------------------------------------------------------------
__global__ __launch_bounds__(256) void k3_gemv_v(const float* __restrict__ W,
                                                 const float* __restrict__ bias) {
    const int bh = blockIdx.y;
    __shared__ float ss[8 * CDIM];   // 32 KB
    const int tid = threadIdx.x;
    for (int i = tid; i < 8 * CDIM; i += 256) ss[i] = g_s[bh * 8 * CDIM + i];
    __syncthreads();

    const int wid = tid >> 5, lane = tid & 31;
    const int d = blockIdx.x * 8 + wid;
    const float4* wrow = reinterpret_cast<const float4*>(W + (size_t)d * CDIM);

    float acc[8] = {0.f, 0.f, 0.f, 0.f, 0.f, 0.f, 0.f, 0.f};
    #pragma unroll
    for (int j = 0; j < 8; j++) {
        const float4 wv = wrow[lane + 32 * j];
        #pragma unroll
        for (int q = 0; q < 8; q++) {
            const float4 sv = reinterpret_cast<const float4*>(ss + q * CDIM)[lane + 32 * j];
            acc[q] += wv.x * sv.x + wv.y * sv.y + wv.z * sv.z + wv.w * sv.w;
        }
    }
    #pragma unroll
    for (int q = 0; q < 8; q++)
        #pragma unroll
        for (int o = 16; o; o >>= 1)
            acc[q] += __shfl_xor_sync(0xFFFFFFFFu, acc[q], o);

    if (lane == 0) {
        const float bs = (float)NPOS * bias[d];
        #pragma unroll
        for (int q = 0; q < 8; q++)
            g_vsum[(bh * 8 + q) * CDIM + d] = acc[q] + bs;
    }
}

// ---------------------------------------------------------------------------
// k4: y[b,d'] = vsum[b,:] . Wo[d',:] + bo[d'], then broadcast-write the full
// output row out[b, d', 0..1023] = y[b,d'] (fuses the 64 MB expansion).
// ---------------------------------------------------------------------------
__global__ __launch_bounds__(256) void k4_gemv_o_bcast(const float* __restrict__ W,
                                                       const float* __restrict__ bias,
                                                       float* __restrict__ out) {
    const int bh = blockIdx.y;
    __shared__ float ss[8 * CDIM];
    const int tid = threadIdx.x;
    for (int i = tid; i < 8 * CDIM; i += 256) ss[i] = g_vsum[bh * 8 * CDIM + i];
    __syncthreads();

    const int wid = tid >> 5, lane = tid & 31;
    const int d = blockIdx.x * 8 + wid;
    const float4* wrow = reinterpret_cast<const float4*>(W + (size_t)d * CDIM);

    float acc[8] = {0.f, 0.f, 0.f, 0.f, 0.f, 0.f, 0.f, 0.f};
    #pragma unroll
    for (int j = 0; j < 8; j++) {
        const float4 wv = wrow[lane + 32 * j];
        #pragma unroll
        for (int q = 0; q < 8; q++) {
            const float4 sv = reinterpret_cast<const float4*>(ss + q * CDIM)[lane + 32 * j];
            acc[q] += wv.x * sv.x + wv.y * sv.y + wv.z * sv.z + wv.w * sv.w;
        }
    }
    // Butterfly reduce: ALL lanes end with the full sum, so all 32 lanes write.
    #pragma unroll
    for (int q = 0; q < 8; q++)
        #pragma unroll
        for (int o = 16; o; o >>= 1)
            acc[q] += __shfl_xor_sync(0xFFFFFFFFu, acc[q], o);

    const float bs = bias[d];
    #pragma unroll
    for (int q = 0; q < 8; q++) {
        const float v = acc[q] + bs;
        const float4 vv = make_float4(v, v, v, v);
        float4* orow = reinterpret_cast<float4*>(
            out + ((size_t)(bh * 8 + q) * CDIM + d) * NPOS);
        #pragma unroll
        for (int t = 0; t < 8; t++) orow[lane + 32 * t] = vv;
    }
}

extern "C" void kernel_launch(void* const* d_in, const int* in_sizes, int n_in,
                              void* d_out, int out_size) {
    const float* x     = (const float*)d_in[0];
    const float* gamma = (const float*)d_in[1];
    const float* beta  = (const float*)d_in[2];
    // d_in[3..6] = Wq,bq,Wk,bk : provably unused (softmax rows sum to 1).
    const float* Wv    = (const float*)d_in[7];
    const float* bv    = (const float*)d_in[8];
    const float* Wo    = (const float*)d_in[9];
    const float* bo    = (const float*)d_in[10];
    float* out = (float*)d_out;

    k1_stats<<<BSZ * NGRP, 256>>>(x, gamma);
    k2_colsum<<<BSZ, 1024>>>(gamma, beta);
    k3_gemv_v<<<dim3(CDIM / 8, 2), 256>>>(Wv, bv);
    k4_gemv_o_bcast<<<dim3(CDIM / 8, 2), 256>>>(Wo, bo, out);
}

// round 2
// speedup vs baseline: 1.0006x; 1.0006x over previous
#include <cuda_runtime.h>

// Attention_72447508349519 — algebraic collapse:
//   softmax rows sum to 1 and einsum('bqk,bvd->bqd') contracts k and v
//   independently, so out[b,q,d] = sum_n v[b,n,d] for every q.
//   => GroupNorm stats + per-channel weighted sums (1 pass over x),
//      two 16x1024x1024 GEMVs (Wv then Wo), broadcast-write the result.
// Unused inputs: Wq,bq,Wk,bk.

#define BSZ   16
#define CDIM  1024   // channels c (== DIM)
#define NPOS  1024   // N = h*w
#define NGRP  32     // GroupNorm groups (along N)
#define GROWS 32     // N-rows per group
#define EPS   1e-5f

// Scratch (static device globals — no dynamic allocation).
__device__ float g_P[BSZ * NGRP * CDIM];   // P[b,g,c] = sum_{n in g} gamma[n]*x[b,c,n]
__device__ float g_mean[BSZ * NGRP];
__device__ float g_rstd[BSZ * NGRP];
__device__ float g_s[BSZ * CDIM];          // s[b,c] = sum_n norm_x[b,n,c]
__device__ float g_vsum[BSZ * CDIM];       // vsum[b,d] = sum_n v[b,n,d]

// ---------------------------------------------------------------------------
// k1: per (b,g) block — one pass over the 32x1024 slab of x.
// Computes group mean/rstd and gamma-weighted per-channel partial sums P.
// Lane mapping: 8 lanes per channel-row (one float4 each) => every warp
// LDG.128 touches exactly 4 fully-used 128B lines.
// ---------------------------------------------------------------------------
__global__ __launch_bounds__(256) void k1_stats(const float* __restrict__ x,
                                                const float* __restrict__ gamma) {
    const int b = blockIdx.x >> 5;
    const int g = blockIdx.x & 31;
    const int tid = threadIdx.x;

    __shared__ float sg[GROWS];
    if (tid < GROWS) sg[tid] = gamma[g * GROWS + tid];
    __syncthreads();

    const int fj = tid & 7;    // float4 slot within the 32-float row
    const int gq = tid >> 3;   // row-group 0..31 (channel = gq + 32*k)
    const float w0 = sg[fj * 4 + 0], w1 = sg[fj * 4 + 1];
    const float w2 = sg[fj * 4 + 2], w3 = sg[fj * 4 + 3];

    const float* xb = x + (size_t)b * CDIM * NPOS + g * GROWS;

    float tsum = 0.f, tsq = 0.f;
    #pragma unroll 4
    for (int k = 0; k < 32; k++) {
        const int c = gq + 32 * k;
        const float4 v = reinterpret_cast<const float4*>(xb + (size_t)c * NPOS)[fj];
        tsum += v.x + v.y + v.z + v.w;
        tsq  += v.x * v.x + v.y * v.y + v.z * v.z + v.w * v.w;
        float pw = w0 * v.x + w1 * v.y + w2 * v.z + w3 * v.w;
        // reduce the 8 lanes covering this row (xor over lane bits 0..2)
        pw += __shfl_xor_sync(0xFFFFFFFFu, pw, 1);
        pw += __shfl_xor_sync(0xFFFFFFFFu, pw, 2);
        pw += __shfl_xor_sync(0xFFFFFFFFu, pw, 4);
        if (fj == 0) g_P[(b * NGRP + g) * CDIM + c] = pw;
    }

    // Block reduction of tsum/tsq over all 256 threads.
    #pragma unroll
    for (int o = 16; o; o >>= 1) {
        tsum += __shfl_xor_sync(0xFFFFFFFFu, tsum, o);
        tsq  += __shfl_xor_sync(0xFFFFFFFFu, tsq,  o);
    }
    __shared__ float reds[8], redq[8];
    const int wid = tid >> 5, lane = tid & 31;
    if (lane == 0) { reds[wid] = tsum; redq[wid] = tsq; }
    __syncthreads();
    if (tid == 0) {
        float S = 0.f, Q = 0.f;
        #pragma unroll
        for (int w = 0; w < 8; w++) { S += reds[w]; Q += redq[w]; }
        const float inv = 1.f / (float)(GROWS * CDIM);
        const float m = S * inv;
        const float var = Q * inv - m * m;
        g_mean[b * NGRP + g] = m;
        g_rstd[b * NGRP + g] = rsqrtf(var + EPS);
    }
}

// ---------------------------------------------------------------------------
// k2: s[b,c] = sum_g rstd[b,g]*(P[b,g,c] - mean[b,g]*Gam_g) + sum_n beta[n]
// ---------------------------------------------------------------------------
__global__ __launch_bounds__(1024) void k2_colsum(const float* __restrict__ gamma,
                                                  const float* __restrict__ beta) {
    const int b = blockIdx.x;
    const int tid = threadIdx.x;

    __shared__ float sgam[CDIM];
    __shared__ float sGam[NGRP];
    __shared__ float sm[NGRP], sr[NGRP];
    __shared__ float redb[32];
    __shared__ float sB;

    sgam[tid] = gamma[tid];
    float bb = beta[tid];
    #pragma unroll
    for (int o = 16; o; o >>= 1) bb += __shfl_xor_sync(0xFFFFFFFFu, bb, o);
    const int wid = tid >> 5, lane = tid & 31;
    if (lane == 0) redb[wid] = bb;
    if (tid < NGRP) { sm[tid] = g_mean[b * NGRP + tid]; sr[tid] = g_rstd[b * NGRP + tid]; }
    __syncthreads();

    if (tid < NGRP) {
        float t = 0.f;
        #pragma unroll
        for (int j = 0; j < GROWS; j++) t += sgam[tid * GROWS + j];
        sGam[tid] = t;
    }
    if (tid == 0) {
        float t = 0.f;
        #pragma unroll
        for (int w = 0; w < 32; w++) t += redb[w];
        sB = t;
    }
    __syncthreads();

    float acc = sB;
    const float* Pb = g_P + b * NGRP * CDIM + tid;
    #pragma unroll
    for (int g = 0; g < NGRP; g++)
        acc += sr[g] * (Pb[g * CDIM] - sm[g] * sGam[g]);
    g_s[b * CDIM + tid] = acc;
}

// ---------------------------------------------------------------------------
// k3: vsum[b,d] = s[b,:] . Wv[d,:] + 1024*bv[d]
// grid (128, 2): x = group of 8 output rows d, y = batch half (8 batches).
// One warp per d; lanes stride c with float4; 8-batch accumulators.
// ---------------------------------------------------------------------------
__global__ __launch_bounds__(256) void k3_gemv_v(const float* __restrict__ W,
                                                 const float* __restrict__ bias) {
    const int bh = blockIdx.y;
    __shared__ float ss[8 * CDIM];   // 32 KB
    const int tid = threadIdx.x;
    for (int i = tid; i < 8 * CDIM; i += 256) ss[i] = g_s[bh * 8 * CDIM + i];
    __syncthreads();

    const int wid = tid >> 5, lane = tid & 31;
    const int d = blockIdx.x * 8 + wid;
    const float4* wrow = reinterpret_cast<const float4*>(W + (size_t)d * CDIM);

    float acc[8] = {0.f, 0.f, 0.f, 0.f, 0.f, 0.f, 0.f, 0.f};
    #pragma unroll
    for (int j = 0; j < 8; j++) {
        const float4 wv = wrow[lane + 32 * j];
        #pragma unroll
        for (int q = 0; q < 8; q++) {
            const float4 sv = reinterpret_cast<const float4*>(ss + q * CDIM)[lane + 32 * j];
            acc[q] += wv.x * sv.x + wv.y * sv.y + wv.z * sv.z + wv.w * sv.w;
        }
    }
    #pragma unroll
    for (int q = 0; q < 8; q++)
        #pragma unroll
        for (int o = 16; o; o >>= 1)
            acc[q] += __shfl_xor_sync(0xFFFFFFFFu, acc[q], o);

    if (lane == 0) {
        const float bs = (float)NPOS * bias[d];
        #pragma unroll
        for (int q = 0; q < 8; q++)
            g_vsum[(bh * 8 + q) * CDIM + d] = acc[q] + bs;
    }
}

// ---------------------------------------------------------------------------
// k4: y[b,d'] = vsum[b,:] . Wo[d',:] + bo[d'], then broadcast-write the full
// output row out[b, d', 0..1023] = y[b,d'] (fuses the 64 MB expansion).
// ---------------------------------------------------------------------------
__global__ __launch_bounds__(256) void k4_gemv_o_bcast(const float* __restrict__ W,
                                                       const float* __restrict__ bias,
                                                       float* __restrict__ out) {
    const int bh = blockIdx.y;
    __shared__ float ss[8 * CDIM];
    const int tid = threadIdx.x;
    for (int i = tid; i < 8 * CDIM; i += 256) ss[i] = g_vsum[bh * 8 * CDIM + i];
    __syncthreads();

    const int wid = tid >> 5, lane = tid & 31;
    const int d = blockIdx.x * 8 + wid;
    const float4* wrow = reinterpret_cast<const float4*>(W + (size_t)d * CDIM);

    float acc[8] = {0.f, 0.f, 0.f, 0.f, 0.f, 0.f, 0.f, 0.f};
    #pragma unroll
    for (int j = 0; j < 8; j++) {
        const float4 wv = wrow[lane + 32 * j];
        #pragma unroll
        for (int q = 0; q < 8; q++) {
            const float4 sv = reinterpret_cast<const float4*>(ss + q * CDIM)[lane + 32 * j];
            acc[q] += wv.x * sv.x + wv.y * sv.y + wv.z * sv.z + wv.w * sv.w;
        }
    }
    // Butterfly reduce: ALL lanes end with the full sum, so all 32 lanes write.
    #pragma unroll
    for (int q = 0; q < 8; q++)
        #pragma unroll
        for (int o = 16; o; o >>= 1)
            acc[q] += __shfl_xor_sync(0xFFFFFFFFu, acc[q], o);

    const float bs = bias[d];
    #pragma unroll
    for (int q = 0; q < 8; q++) {
        const float v = acc[q] + bs;
        const float4 vv = make_float4(v, v, v, v);
        float4* orow = reinterpret_cast<float4*>(
            out + ((size_t)(bh * 8 + q) * CDIM + d) * NPOS);
        #pragma unroll
        for (int t = 0; t < 8; t++) orow[lane + 32 * t] = vv;
    }
}

extern "C" void kernel_launch(void* const* d_in, const int* in_sizes, int n_in,
                              void* d_out, int out_size) {
    const float* x     = (const float*)d_in[0];
    const float* gamma = (const float*)d_in[1];
    const float* beta  = (const float*)d_in[2];
    // d_in[3..6] = Wq,bq,Wk,bk : provably unused (softmax rows sum to 1).
    const float* Wv    = (const float*)d_in[7];
    const float* bv    = (const float*)d_in[8];
    const float* Wo    = (const float*)d_in[9];
    const float* bo    = (const float*)d_in[10];
    float* out = (float*)d_out;

    k1_stats<<<BSZ * NGRP, 256>>>(x, gamma);
    k2_colsum<<<BSZ, 1024>>>(gamma, beta);
    k3_gemv_v<<<dim3(CDIM / 8, 2), 256>>>(Wv, bv);
    k4_gemv_o_bcast<<<dim3(CDIM / 8, 2), 256>>>(Wo, bo, out);
}